// round 2
// baseline (speedup 1.0000x reference)
#include <cuda_runtime.h>

// Problem constants (N=8, C=16, H=512, W=512)
#define NC    16
#define HW    262144              // H*W
#define NPIX  2097152             // N*H*W
#define HW4   (HW/4)
#define NG    (NPIX/4)            // float4 pixel-groups

#define SMOOTH_F 1e-8f
#define ALPHA_SMOOTH_F 0.1f

// Scratch (no device allocation allowed)
__device__ unsigned int g_counts[NC];
__device__ float        g_alpha[NC];
__device__ double       g_sum;

// ---------------------------------------------------------------- zero
__global__ void k_zero() {
    int t = threadIdx.x;
    if (t < NC) g_counts[t] = 0u;
    if (t == 0) g_sum = 0.0;
}

// ---------------------------------------------------------------- histogram (target: int32)
__global__ void k_hist(const int4* __restrict__ tgt4) {
    __shared__ unsigned int sh[NC];
    if (threadIdx.x < NC) sh[threadIdx.x] = 0u;
    __syncthreads();
    int stride = gridDim.x * blockDim.x;
    for (int i = blockIdx.x * blockDim.x + threadIdx.x; i < NPIX / 4; i += stride) {
        int4 t = tgt4[i];
        atomicAdd(&sh[t.x & 15], 1u);
        atomicAdd(&sh[t.y & 15], 1u);
        atomicAdd(&sh[t.z & 15], 1u);
        atomicAdd(&sh[t.w & 15], 1u);
    }
    __syncthreads();
    if (threadIdx.x < NC) atomicAdd(&g_counts[threadIdx.x], sh[threadIdx.x]);
}

// ---------------------------------------------------------------- adaptive alpha (1 warp)
__global__ void k_alpha() {
    int c = threadIdx.x;
    float cnt = (c < NC) ? (float)g_counts[c] : 0.0f;
    float freq = cnt / (float)NPIX;
    float w = 1.0f / (freq + ALPHA_SMOOTH_F);
    float wp = (cnt > 0.0f) ? w : 0.0f;
    #pragma unroll
    for (int o = 16; o; o >>= 1) wp += __shfl_xor_sync(0xffffffffu, wp, o);
    if (c < NC) g_alpha[c] = (cnt > 0.0f) ? (w / wp) : 1.0f;
}

// ---------------------------------------------------------------- main loss
__global__ void __launch_bounds__(256) k_loss(const float4* __restrict__ lg,
                                              const int4* __restrict__ tgt4) {
    __shared__ float s_alpha[NC];
    if (threadIdx.x < NC) s_alpha[threadIdx.x] = g_alpha[threadIdx.x];
    __syncthreads();

    unsigned g   = blockIdx.x * blockDim.x + threadIdx.x;   // < NG exactly
    unsigned n   = g / HW4;
    unsigned hwq = g % HW4;
    const float4* base = lg + (size_t)n * NC * HW4 + hwq;

    // 16 channels x 4 pixels, fully resident in registers
    float4 x[NC];
    #pragma unroll
    for (int c = 0; c < NC; c++) x[c] = base[(size_t)c * HW4];

    int4 t4 = tgt4[g];
    int t0 = t4.x & 15, t1 = t4.y & 15, t2 = t4.z & 15, t3 = t4.w & 15;

    float acc = 0.0f;
    #pragma unroll
    for (int j = 0; j < 4; j++) {
        int tj = (j == 0) ? t0 : (j == 1) ? t1 : (j == 2) ? t2 : t3;
        float v[NC];
        #pragma unroll
        for (int c = 0; c < NC; c++) {
            float4 xv = x[c];
            v[c] = (j == 0) ? xv.x : (j == 1) ? xv.y : (j == 2) ? xv.z : xv.w;
        }
        float mx = v[0];
        #pragma unroll
        for (int c = 1; c < NC; c++) mx = fmaxf(mx, v[c]);
        float se = 0.0f, et = 0.0f;
        #pragma unroll
        for (int c = 0; c < NC; c++) {
            float e = __expf(v[c] - mx);
            se += e;
            et = (c == tj) ? e : et;     // predicated select, no spill
        }
        float pt = et / se;
        float om = 1.0f - pt + SMOOTH_F;
        float focal = s_alpha[tj] * (om * om) * (-__logf(pt + SMOOTH_F));
        acc += focal;
    }

    // warp reduce -> block reduce -> one double atomic per block
    #pragma unroll
    for (int o = 16; o; o >>= 1) acc += __shfl_xor_sync(0xffffffffu, acc, o);
    __shared__ float wsum[8];
    int lane = threadIdx.x & 31, wid = threadIdx.x >> 5;
    if (lane == 0) wsum[wid] = acc;
    __syncthreads();
    if (threadIdx.x == 0) {
        float s = 0.0f;
        #pragma unroll
        for (int i = 0; i < 8; i++) s += wsum[i];
        atomicAdd(&g_sum, (double)s);
    }
}

// ---------------------------------------------------------------- finalize
__global__ void k_fin(float* out) {
    out[0] = (float)(g_sum / ((double)NPIX + 1e-8));
}

extern "C" void kernel_launch(void* const* d_in, const int* in_sizes, int n_in,
                              void* d_out, int out_size) {
    const float* logits = (const float*)d_in[0];
    const int*   target = (const int*)d_in[1];
    float* out = (float*)d_out;

    k_zero<<<1, 32>>>();
    k_hist<<<512, 256>>>((const int4*)target);
    k_alpha<<<1, 32>>>();
    k_loss<<<NG / 256, 256>>>((const float4*)logits, (const int4*)target);
    k_fin<<<1, 1>>>(out);
}